// round 14
// baseline (speedup 1.0000x reference)
#include <cuda_runtime.h>
#include <math_constants.h>
#include <cstdint>

#define B_PAT 4096
#define N_DIS 10000
#define DIM   256
#define NB    80                 // rank blocks
#define BLK   128                // ranks per block
#define NRANK (NB*BLK)           // 10240 padded ranks
#define L2EF  1.4426950408889634f
#define LEAKY 0.2f

// ---------------- device globals (no allocation) ----------------
__device__ float g_sp[B_PAT];
__device__ float g_sn[N_DIS];
__device__ int   g_rank[N_DIS];
__device__ int   g_ord[NRANK];          // rank -> node (pad: unused, guarded)
__device__ float g_snsort[NRANK];       // sorted sn values (ranks < N_DIS)
__device__ float g_B1[NB][DIM], g_B2[NB][DIM];       // block sums
__device__ float g_Off1[NB][DIM], g_Off2[NB][DIM];   // block offsets
__device__ float g_sufs[NRANK];         // scalar suffix sums of F1
__device__ float g_pres[NRANK];         // scalar prefix sums of F2
__device__ float g_SUF1[NRANK][DIM];    // suffix sums of F1 * dn  (10.5 MB)
__device__ float g_PRE2[NRANK][DIM];    // prefix sums of F2 * dn  (10.5 MB)

__device__ __forceinline__ float ex2(float x) {
    float r; asm("ex2.approx.ftz.f32 %0, %1;" : "=f"(r) : "f"(x)); return r;
}

// ---------------- kernel 1: sp, sn dot products (+ zero ranks) ----------------
__global__ __launch_bounds__(256) void k_scores(
    const float* __restrict__ pf, const float* __restrict__ dn,
    const float* __restrict__ ak)
{
    int tid  = threadIdx.x;
    int lane = tid & 31;
    int gw   = blockIdx.x * 8 + (tid >> 5);

    float v = 0.0f;
    if (gw < B_PAT) {
        const float4* r = (const float4*)(pf + (size_t)gw * DIM);
        const float4* w = (const float4*)ak;
        #pragma unroll
        for (int k = 0; k < 2; k++) {
            float4 x  = r[lane * 2 + k];
            float4 ww = __ldg(&w[lane * 2 + k]);
            v += x.x * ww.x + x.y * ww.y + x.z * ww.z + x.w * ww.w;
        }
    } else if (gw < B_PAT + N_DIS) {
        const float4* r = (const float4*)(dn + (size_t)(gw - B_PAT) * DIM);
        const float4* w = (const float4*)(ak + DIM);
        #pragma unroll
        for (int k = 0; k < 2; k++) {
            float4 x  = r[lane * 2 + k];
            float4 ww = __ldg(&w[lane * 2 + k]);
            v += x.x * ww.x + x.y * ww.y + x.z * ww.z + x.w * ww.w;
        }
    }
    #pragma unroll
    for (int o = 16; o; o >>= 1) v += __shfl_xor_sync(0xffffffffu, v, o);

    if (lane == 0) {
        if (gw < B_PAT) {
            g_sp[gw] = v;
        } else if (gw < B_PAT + N_DIS) {
            g_sn[gw - B_PAT]   = v;
            g_rank[gw - B_PAT] = 0;
        }
    }
}

// ---------------- kernel 2: counting rank (lexicographic (sn, idx)) ----------------
// grid (40, 8): node group x domain split. Deterministic: integer atomics.
__global__ __launch_bounds__(256) void k_rank()
{
    __shared__ float sm[1250];
    const int tid   = threadIdx.x;
    const int n     = blockIdx.x * 256 + tid;
    const int mbase = blockIdx.y * 1250;

    for (int i = tid; i < 1250; i += 256) sm[i] = g_sn[mbase + i];
    __syncthreads();

    const bool valid = (n < N_DIS);
    const float sn = valid ? g_sn[n] : 0.0f;
    int cnt = 0;
    #pragma unroll 4
    for (int i = 0; i < 1250; i++) {
        float v = sm[i];
        int   m = mbase + i;
        cnt += (v < sn) || (v == sn && m < n);
    }
    if (valid) atomicAdd(&g_rank[n], cnt);
}

// ---------------- kernel 3: scatter into sorted order ----------------
__global__ __launch_bounds__(256) void k_scat()
{
    int n = blockIdx.x * 256 + threadIdx.x;
    if (n < N_DIS) {
        int r = g_rank[n];
        g_ord[r]    = n;
        g_snsort[r] = g_sn[n];
    }
}

// ---------------- kernel 4: block sums of F1*dn and F2*dn ----------------
// grid NB, 256 threads (one per dim)
__global__ __launch_bounds__(256) void k_scanA(const float* __restrict__ dn)
{
    __shared__ float sF1[BLK], sF2[BLK];
    __shared__ int   sOrd[BLK];
    const int tid = threadIdx.x;
    const int j   = blockIdx.x;

    if (tid < BLK) {
        int r = j * BLK + tid;
        float f1 = 0.0f, f2 = 0.0f; int o = 0;
        if (r < N_DIS) {
            float key = g_snsort[r];
            f1 = ex2(key * L2EF);
            f2 = ex2(key * (LEAKY * L2EF));
            o  = g_ord[r];
        }
        sF1[tid] = f1; sF2[tid] = f2; sOrd[tid] = o;
    }
    __syncthreads();

    const int d = tid;
    float s1 = 0.0f, s2 = 0.0f;
    #pragma unroll 4
    for (int i = 0; i < BLK; i++) {
        float v = __ldg(&dn[(size_t)sOrd[i] * DIM + d]);   // f=0 for pads
        s1 += sF1[i] * v;
        s2 += sF2[i] * v;
    }
    g_B1[j][d] = s1;
    g_B2[j][d] = s2;
}

// ---------------- kernel 5: block offsets (vector) + full scalar scans ----------------
// 1 CTA, 256 threads.
__global__ __launch_bounds__(256) void k_scanB()
{
    const int tid = threadIdx.x;

    // vector block offsets: Off1[j] = sum of blocks after j; Off2[j] = before j
    {
        const int d = tid;
        float run = 0.0f;
        for (int j = NB - 1; j >= 0; j--) { g_Off1[j][d] = run; run += g_B1[j][d]; }
        run = 0.0f;
        for (int j = 0; j < NB; j++)      { g_Off2[j][d] = run; run += g_B2[j][d]; }
    }

    // scalar scans: thread t owns ranks [t*40, t*40+40)
    float t1 = 0.0f, t2 = 0.0f;
    for (int i = 0; i < 40; i++) {
        int r = tid * 40 + i;
        if (r < N_DIS) {
            float key = g_snsort[r];
            t1 += ex2(key * L2EF);
            t2 += ex2(key * (LEAKY * L2EF));
        }
    }
    __shared__ float p1[256], p2[256], o1[256], o2[256];
    p1[tid] = t1; p2[tid] = t2;
    __syncthreads();
    if (tid == 0) {
        float r1 = 0.0f;
        for (int t = 255; t >= 0; t--) { o1[t] = r1; r1 += p1[t]; }
        float r2 = 0.0f;
        for (int t = 0; t < 256; t++)  { o2[t] = r2; r2 += p2[t]; }
    }
    __syncthreads();

    float run1 = o1[tid];
    for (int i = 39; i >= 0; i--) {
        int r = tid * 40 + i;
        if (r < N_DIS) run1 += ex2(g_snsort[r] * L2EF);
        g_sufs[r] = run1;                       // suffix incl. r
    }
    float run2 = o2[tid];
    for (int i = 0; i < 40; i++) {
        int r = tid * 40 + i;
        g_pres[r] = run2;                       // prefix excl. r
        if (r < N_DIS) run2 += ex2(g_snsort[r] * (LEAKY * L2EF));
    }
}

// ---------------- kernel 6: materialize SUF1 / PRE2 ----------------
// grid NB, 256 threads (one per dim)
__global__ __launch_bounds__(256) void k_scanC(const float* __restrict__ dn)
{
    __shared__ float sF1[BLK], sF2[BLK];
    __shared__ int   sOrd[BLK];
    const int tid = threadIdx.x;
    const int j   = blockIdx.x;

    if (tid < BLK) {
        int r = j * BLK + tid;
        float f1 = 0.0f, f2 = 0.0f; int o = 0;
        if (r < N_DIS) {
            float key = g_snsort[r];
            f1 = ex2(key * L2EF);
            f2 = ex2(key * (LEAKY * L2EF));
            o  = g_ord[r];
        }
        sF1[tid] = f1; sF2[tid] = f2; sOrd[tid] = o;
    }
    __syncthreads();

    const int d = tid;
    float run2 = g_Off2[j][d];
    for (int i = 0; i < BLK; i++) {
        int r = j * BLK + i;
        g_PRE2[r][d] = run2;                    // prefix excl. r
        run2 += sF2[i] * __ldg(&dn[(size_t)sOrd[i] * DIM + d]);
    }
    float run1 = g_Off1[j][d];
    for (int i = BLK - 1; i >= 0; i--) {
        int r = j * BLK + i;
        run1 += sF1[i] * __ldg(&dn[(size_t)sOrd[i] * DIM + d]);
        g_SUF1[r][d] = run1;                    // suffix incl. r
    }
}

// ---------------- kernel 7: per-patient combine ----------------
// grid B_PAT/4, 256 threads: 4 patients x 64 lanes (4 dims each)
__global__ __launch_bounds__(256) void k_fin(
    const float* __restrict__ pf, float* __restrict__ out)
{
    const int tid = threadIdx.x;
    const int pat = tid >> 6;
    const int l   = tid & 63;
    const int b   = blockIdx.x * 4 + pat;

    const float sp = g_sp[b];
    const float th = -sp;

    // lower_bound over sorted sn: first rank with sn >= th  (branch1 set)
    int lo = 0, hi = N_DIS;
    while (lo < hi) {
        int mid = (lo + hi) >> 1;
        if (__ldg(&g_snsort[mid]) < th) lo = mid + 1; else hi = mid;
    }
    const int k = lo;                          // 0..N_DIS (SUF1[N_DIS] valid: pad rows)

    const float E1 = ex2(sp * L2EF);
    const float E2 = ex2(sp * (LEAKY * L2EF));
    const float den = E1 * __ldg(&g_sufs[k]) + E2 * __ldg(&g_pres[k]);
    const float inv = 1.0f / den;

    const int d0 = l * 4;
    float4 s = *(const float4*)&g_SUF1[k][d0];
    float4 p = *(const float4*)&g_PRE2[k][d0];
    float4 x = *(const float4*)&pf[(size_t)b * DIM + d0];
    float4 o;
    o.x = x.x + (E1 * s.x + E2 * p.x) * inv;
    o.y = x.y + (E1 * s.y + E2 * p.y) * inv;
    o.z = x.z + (E1 * s.z + E2 * p.z) * inv;
    o.w = x.w + (E1 * s.w + E2 * p.w) * inv;
    *(float4*)&out[(size_t)b * DIM + d0] = o;
}

// ---------------- launch ----------------
extern "C" void kernel_launch(void* const* d_in, const int* in_sizes, int n_in,
                              void* d_out, int out_size)
{
    const float* pf = (const float*)d_in[0];   // [4096, 256]
    const float* dn = (const float*)d_in[1];   // [10000, 256]
    const float* ak = (const float*)d_in[2];   // [512, 1]
    float* out = (float*)d_out;

    k_scores<<<(B_PAT + N_DIS) / 8, 256>>>(pf, dn, ak);
    k_rank <<<dim3(40, 8), 256>>>();
    k_scat <<<40, 256>>>();
    k_scanA<<<NB, 256>>>(dn);
    k_scanB<<<1, 256>>>();
    k_scanC<<<NB, 256>>>(dn);
    k_fin  <<<B_PAT / 4, 256>>>(pf, out);
}